// round 4
// baseline (speedup 1.0000x reference)
#include <cuda_runtime.h>
#include <math_constants.h>

// Problem constants
#define BATCH   64
#define SEQL    256
#define EDIM    512
#define SDIM    1024
#define KDIM    1024   // 2*E
#define NCLASS  2

// GEMM tile config
#define BM 128
#define BN 128
#define BKK 16
#define TM 8
#define TN 8

// Scratch (static device globals; no allocations allowed)
__device__ float g_embs[BATCH * SEQL * EDIM];     // 33.5 MB gathered embeddings
__device__ float g_sentpre[BATCH * SDIM];         // pre-sigmoid max-pool accumulator

__device__ __forceinline__ void atomicMaxFloat(float* addr, float val) {
    // standard bit-trick: positive floats order like ints, negative like reversed unsigned
    if (val >= 0.0f) {
        atomicMax(reinterpret_cast<int*>(addr), __float_as_int(val));
    } else {
        atomicMin(reinterpret_cast<unsigned int*>(addr), __float_as_uint(val));
    }
}

// ---------------------------------------------------------------------------
// Kernel 1: embedding gather.  One block per (b,l) row, 128 threads x float4.
// ---------------------------------------------------------------------------
__global__ void gather_kernel(const int* __restrict__ inputs,
                              const float* __restrict__ emb_table) {
    int row = blockIdx.x;                 // 0 .. BATCH*SEQL-1
    int tok = inputs[row];
    const float4* src = reinterpret_cast<const float4*>(emb_table + (size_t)tok * EDIM);
    float4* dst = reinterpret_cast<float4*>(g_embs + (size_t)row * EDIM);
    dst[threadIdx.x] = src[threadIdx.x];  // 128 threads * 4 floats = 512 = EDIM
}

// ---------------------------------------------------------------------------
// Kernel 2: init max accumulator to -inf
// ---------------------------------------------------------------------------
__global__ void init_kernel() {
    int i = blockIdx.x * blockDim.x + threadIdx.x;
    if (i < BATCH * SDIM) g_sentpre[i] = -CUDART_INF_F;
}

// ---------------------------------------------------------------------------
// Kernel 3: fused conv GEMM + max-pool.
//   conv[b,l,s] = dot(g_embs[b, l*512 : l*512+1024], Wc[s,:]) + bc[s]
//   (pairs row l is contiguous in g_embs with row stride 512)
//   g_sentpre[b,s] = max_l conv[b,l,s]   (via block reduce + atomicMaxFloat)
// Grid: (SDIM/BN, ceil(255/BM), BATCH), 256 threads.
// ---------------------------------------------------------------------------
__global__ __launch_bounds__(256) void conv_max_kernel(
    const float* __restrict__ Wc, const float* __restrict__ bc)
{
    const int b  = blockIdx.z;
    const int m0 = blockIdx.y * BM;     // l-tile offset
    const int n0 = blockIdx.x * BN;     // s-tile offset
    const float* A = g_embs + (size_t)b * SEQL * EDIM;

    __shared__ float As[BKK][BM];
    __shared__ float Bs[BKK][BN];
    __shared__ float red[16][BN];

    const int tid  = threadIdx.x;
    const int trow = tid >> 4;          // 0..15
    const int tcol = tid & 15;          // 0..15
    const int tm   = trow * TM;
    const int tn   = tcol * TN;

    float acc[TM][TN];
#pragma unroll
    for (int i = 0; i < TM; i++)
#pragma unroll
        for (int j = 0; j < TN; j++) acc[i][j] = 0.0f;

    for (int k0 = 0; k0 < KDIM; k0 += BKK) {
        // --- load A tile: 128 rows x 16 cols = 512 float4, 2 per thread ---
#pragma unroll
        for (int q = 0; q < 2; q++) {
            int lid = tid + 256 * q;
            int ar  = lid >> 2;               // 0..127
            int ac  = (lid & 3) << 2;         // 0,4,8,12
            int gl  = m0 + ar;                // global l
            float4 v = make_float4(0.f, 0.f, 0.f, 0.f);
            if (gl < SEQL - 1)
                v = *reinterpret_cast<const float4*>(A + (size_t)gl * EDIM + k0 + ac);
            As[ac + 0][ar] = v.x; As[ac + 1][ar] = v.y;
            As[ac + 2][ar] = v.z; As[ac + 3][ar] = v.w;
        }
        // --- load B tile: Wc[s,k], 128 rows x 16 cols ---
#pragma unroll
        for (int q = 0; q < 2; q++) {
            int lid = tid + 256 * q;
            int br  = lid >> 2;
            int bcc = (lid & 3) << 2;
            float4 v = *reinterpret_cast<const float4*>(
                Wc + (size_t)(n0 + br) * KDIM + k0 + bcc);
            Bs[bcc + 0][br] = v.x; Bs[bcc + 1][br] = v.y;
            Bs[bcc + 2][br] = v.z; Bs[bcc + 3][br] = v.w;
        }
        __syncthreads();

#pragma unroll
        for (int k = 0; k < BKK; k++) {
            float ra[TM], rb[TN];
            // vector reads from smem (8 consecutive floats each)
            *reinterpret_cast<float4*>(&ra[0]) = *reinterpret_cast<const float4*>(&As[k][tm]);
            *reinterpret_cast<float4*>(&ra[4]) = *reinterpret_cast<const float4*>(&As[k][tm + 4]);
            *reinterpret_cast<float4*>(&rb[0]) = *reinterpret_cast<const float4*>(&Bs[k][tn]);
            *reinterpret_cast<float4*>(&rb[4]) = *reinterpret_cast<const float4*>(&Bs[k][tn + 4]);
#pragma unroll
            for (int i = 0; i < TM; i++)
#pragma unroll
                for (int j = 0; j < TN; j++)
                    acc[i][j] = fmaf(ra[i], rb[j], acc[i][j]);
        }
        __syncthreads();
    }

    // --- epilogue: add bias, per-thread max over valid rows ---
    float bcv[TN];
#pragma unroll
    for (int j = 0; j < TN; j++) bcv[j] = __ldg(&bc[n0 + tn + j]);

    float cmax[TN];
#pragma unroll
    for (int j = 0; j < TN; j++) cmax[j] = -CUDART_INF_F;

#pragma unroll
    for (int i = 0; i < TM; i++) {
        int gl = m0 + tm + i;
        if (gl < SEQL - 1) {
#pragma unroll
            for (int j = 0; j < TN; j++)
                cmax[j] = fmaxf(cmax[j], acc[i][j] + bcv[j]);
        }
    }

    // --- tree reduce across the 16 row-groups ---
#pragma unroll
    for (int j = 0; j < TN; j++) red[trow][tn + j] = cmax[j];
    __syncthreads();
#pragma unroll
    for (int st = 8; st > 0; st >>= 1) {
        if (trow < st) {
#pragma unroll
            for (int j = 0; j < TN; j++)
                red[trow][tn + j] = fmaxf(red[trow][tn + j], red[trow + st][tn + j]);
        }
        __syncthreads();
    }
    if (trow == 0) {
#pragma unroll
        for (int j = 0; j < TN; j++)
            atomicMaxFloat(&g_sentpre[(size_t)b * SDIM + n0 + tn + j], red[0][tn + j]);
    }
}

// ---------------------------------------------------------------------------
// Kernel 4: sigmoid + classifier (S->50->2) + log_softmax. One block per b.
// ---------------------------------------------------------------------------
__global__ __launch_bounds__(128) void classifier_kernel(
    const float* __restrict__ W1, const float* __restrict__ b1,
    const float* __restrict__ W2, const float* __restrict__ b2,
    float* __restrict__ out)
{
    const int b = blockIdx.x;
    __shared__ float sent[SDIM];
    __shared__ float h[64];

    for (int i = threadIdx.x; i < SDIM; i += blockDim.x) {
        float v = g_sentpre[(size_t)b * SDIM + i];
        sent[i] = 1.0f / (1.0f + expf(-v));
    }
    __syncthreads();

    const int w    = threadIdx.x >> 5;
    const int lane = threadIdx.x & 31;
    for (int j = w; j < 50; j += 4) {
        float sum = 0.0f;
        const float* wrow = W1 + (size_t)j * SDIM;
        for (int i = lane; i < SDIM; i += 32) sum = fmaf(sent[i], wrow[i], sum);
#pragma unroll
        for (int o = 16; o > 0; o >>= 1) sum += __shfl_down_sync(0xffffffffu, sum, o);
        if (lane == 0) h[j] = sum + b1[j];
    }
    __syncthreads();

    if (threadIdx.x == 0) {
        float l0 = b2[0], l1 = b2[1];
        for (int j = 0; j < 50; j++) {
            l0 = fmaf(h[j], W2[j], l0);
            l1 = fmaf(h[j], W2[50 + j], l1);
        }
        float m   = fmaxf(l0, l1);
        float lse = m + logf(expf(l0 - m) + expf(l1 - m));
        out[b * NCLASS + 0] = l0 - lse;
        out[b * NCLASS + 1] = l1 - lse;
    }
}

// ---------------------------------------------------------------------------
// kernel_launch
// inputs order: inputs(int32), emb_table, Wc, bc, W1, b1, W2, b2
// ---------------------------------------------------------------------------
extern "C" void kernel_launch(void* const* d_in, const int* in_sizes, int n_in,
                              void* d_out, int out_size) {
    const int*   inputs = (const int*)  d_in[0];
    const float* emb    = (const float*)d_in[1];
    const float* Wc     = (const float*)d_in[2];
    const float* bc     = (const float*)d_in[3];
    const float* W1     = (const float*)d_in[4];
    const float* b1     = (const float*)d_in[5];
    const float* W2     = (const float*)d_in[6];
    const float* b2     = (const float*)d_in[7];
    float* out = (float*)d_out;

    gather_kernel<<<BATCH * SEQL, 128>>>(inputs, emb);
    init_kernel<<<(BATCH * SDIM + 255) / 256, 256>>>();

    dim3 grid(SDIM / BN, (SEQL - 1 + BM - 1) / BM, BATCH);
    conv_max_kernel<<<grid, 256>>>(Wc, bc);

    classifier_kernel<<<BATCH, 128>>>(W1, b1, W2, b2, out);
}

// round 5
// speedup vs baseline: 3.2720x; 3.2720x over previous
#include <cuda_runtime.h>
#include <math_constants.h>
#include <cstdint>

// Problem constants
#define BATCH   64
#define SEQL    256
#define EDIM    512
#define SDIM    1024
#define KDIM    1024   // 2*E
#define NCLASS  2

// GEMM tile config (TF32 mma.sync path)
#define BM 128
#define BN 128
#define BK 32
#define LDT 36                    // padded smem row stride (floats): bank-conflict-free frags
#define TILE_FLOATS (128 * LDT)   // one 128x32 tile in smem
#define STAGE_FLOATS (2 * TILE_FLOATS)
#define SMEM_BYTES (2 * STAGE_FLOATS * 4)   // 2 stages * (A+B) = 73728 B

// Scratch (static device globals; no allocations allowed)
__device__ float g_embs[BATCH * SEQL * EDIM];     // gathered embeddings
__device__ float g_sentpre[BATCH * SDIM];         // pre-sigmoid max-pool accumulator
__device__ float g_h[BATCH * 64];                 // hidden layer (50 used)

__device__ __forceinline__ void atomicMaxFloat(float* addr, float val) {
    if (val >= 0.0f) atomicMax(reinterpret_cast<int*>(addr), __float_as_int(val));
    else             atomicMin(reinterpret_cast<unsigned int*>(addr), __float_as_uint(val));
}

__device__ __forceinline__ uint32_t f2tf(float x) {
    uint32_t r;
    asm volatile("cvt.rna.tf32.f32 %0, %1;" : "=r"(r) : "f"(x));
    return r;
}

__device__ __forceinline__ void mma_tf32(float c[4], const uint32_t a[4], const uint32_t b[2]) {
    asm volatile(
        "mma.sync.aligned.m16n8k8.row.col.f32.tf32.tf32.f32 "
        "{%0,%1,%2,%3}, {%4,%5,%6,%7}, {%8,%9}, {%0,%1,%2,%3};"
        : "+f"(c[0]), "+f"(c[1]), "+f"(c[2]), "+f"(c[3])
        : "r"(a[0]), "r"(a[1]), "r"(a[2]), "r"(a[3]), "r"(b[0]), "r"(b[1]));
}

__device__ __forceinline__ void cp_async16(uint32_t saddr, const void* gptr, bool pred) {
    int sz = pred ? 16 : 0;
    asm volatile("cp.async.cg.shared.global [%0], [%1], 16, %2;"
                 :: "r"(saddr), "l"(gptr), "r"(sz));
}

// ---------------------------------------------------------------------------
// Kernel 1: embedding gather.
// ---------------------------------------------------------------------------
__global__ void gather_kernel(const int* __restrict__ inputs,
                              const float* __restrict__ emb_table) {
    int row = blockIdx.x;
    int tok = inputs[row];
    const float4* src = reinterpret_cast<const float4*>(emb_table + (size_t)tok * EDIM);
    float4* dst = reinterpret_cast<float4*>(g_embs + (size_t)row * EDIM);
    dst[threadIdx.x] = src[threadIdx.x];
}

// ---------------------------------------------------------------------------
// Kernel 2: init max accumulator
// ---------------------------------------------------------------------------
__global__ void init_kernel() {
    int i = blockIdx.x * blockDim.x + threadIdx.x;
    if (i < BATCH * SDIM) g_sentpre[i] = -CUDART_INF_F;
}

// ---------------------------------------------------------------------------
// Kernel 3: TF32 tensor-core conv GEMM + fused max-pool.
//   A row l (length 1024) = g_embs[b] + l*512 (overlapping rows, stride 512)
//   B = Wc [1024 x 1024] (n-major, k contiguous)
// Block: 128 threads = 4 warps (2x2), warp tile 64x64, mma m16n8k8.
// Grid: (8 ntiles, 2 mtiles, 64 batches). 2-stage cp.async pipeline.
// ---------------------------------------------------------------------------
__global__ __launch_bounds__(128, 2) void conv_max_kernel(
    const float* __restrict__ Wc, const float* __restrict__ bc)
{
    extern __shared__ float sm[];

    const int b   = blockIdx.z;
    const int m0  = blockIdx.y * BM;
    const int n0  = blockIdx.x * BN;
    const int tid = threadIdx.x;
    const int lane = tid & 31;
    const int warp = tid >> 5;
    const int wm = warp >> 1;         // 0..1
    const int wn = warp & 1;          // 0..1
    const int g  = lane >> 2;         // 0..7
    const int t  = lane & 3;          // 0..3

    const float* Ag = g_embs + (size_t)b * SEQL * EDIM + (size_t)m0 * EDIM;
    const float* Bg = Wc + (size_t)n0 * KDIM;

    const uint32_t smem_u32 = (uint32_t)__cvta_generic_to_shared(sm);

    // --- tile loader: stage st, k-tile kt ---
    auto load_tile = [&](int kt, int st) {
        uint32_t a_base = smem_u32 + (uint32_t)(st * STAGE_FLOATS) * 4u;
        uint32_t b_base = a_base + (uint32_t)TILE_FLOATS * 4u;
#pragma unroll
        for (int i = 0; i < 8; i++) {
            int c   = tid + 128 * i;       // 0..1023
            int row = c >> 3;              // 0..127
            int k4  = (c & 7) << 2;        // 0,4,...,28
            uint32_t soff = (uint32_t)(row * LDT + k4) * 4u;
            // A: row stride EDIM=512 (overlapping pair rows); mask row 255
            bool av = (m0 + row) < (SEQL - 1);
            cp_async16(a_base + soff, Ag + (size_t)row * EDIM + kt * BK + k4, av);
            // B: Wc row stride 1024
            cp_async16(b_base + soff, Bg + (size_t)row * KDIM + kt * BK + k4, true);
        }
    };

    float acc[4][8][4];
#pragma unroll
    for (int mt = 0; mt < 4; mt++)
#pragma unroll
        for (int nt = 0; nt < 8; nt++)
#pragma unroll
            for (int q = 0; q < 4; q++) acc[mt][nt][q] = 0.0f;

    load_tile(0, 0);
    asm volatile("cp.async.commit_group;");

    const int NKT = KDIM / BK;   // 32
    for (int kt = 0; kt < NKT; ++kt) {
        if (kt + 1 < NKT) {
            load_tile(kt + 1, (kt + 1) & 1);
            asm volatile("cp.async.commit_group;");
            asm volatile("cp.async.wait_group 1;");
        } else {
            asm volatile("cp.async.wait_group 0;");
        }
        __syncthreads();

        const float* As = sm + (kt & 1) * STAGE_FLOATS;
        const float* Bs = As + TILE_FLOATS;

#pragma unroll
        for (int ks = 0; ks < 4; ks++) {
            const int k = ks * 8;
            uint32_t af[4][4];
#pragma unroll
            for (int mt = 0; mt < 4; mt++) {
                const float* ap = As + (wm * 64 + mt * 16) * LDT + k;
                af[mt][0] = f2tf(ap[(g    ) * LDT + t    ]);
                af[mt][1] = f2tf(ap[(g + 8) * LDT + t    ]);
                af[mt][2] = f2tf(ap[(g    ) * LDT + t + 4]);
                af[mt][3] = f2tf(ap[(g + 8) * LDT + t + 4]);
            }
            uint32_t bf[8][2];
#pragma unroll
            for (int nt = 0; nt < 8; nt++) {
                const float* bp = Bs + (wn * 64 + nt * 8 + g) * LDT + k;
                bf[nt][0] = f2tf(bp[t]);
                bf[nt][1] = f2tf(bp[t + 4]);
            }
#pragma unroll
            for (int mt = 0; mt < 4; mt++)
#pragma unroll
                for (int nt = 0; nt < 8; nt++)
                    mma_tf32(acc[mt][nt], af[mt], bf[nt]);
        }
        __syncthreads();
    }

    // --- epilogue: per-thread column max over valid rows, shuffle-reduce over g ---
    float cmax[8][2];
#pragma unroll
    for (int nt = 0; nt < 8; nt++) { cmax[nt][0] = -CUDART_INF_F; cmax[nt][1] = -CUDART_INF_F; }

#pragma unroll
    for (int mt = 0; mt < 4; mt++) {
        int r0 = m0 + wm * 64 + mt * 16 + g;
        bool v0 = r0 < (SEQL - 1);
        bool v1 = (r0 + 8) < (SEQL - 1);
#pragma unroll
        for (int nt = 0; nt < 8; nt++) {
            if (v0) {
                cmax[nt][0] = fmaxf(cmax[nt][0], acc[mt][nt][0]);
                cmax[nt][1] = fmaxf(cmax[nt][1], acc[mt][nt][1]);
            }
            if (v1) {
                cmax[nt][0] = fmaxf(cmax[nt][0], acc[mt][nt][2]);
                cmax[nt][1] = fmaxf(cmax[nt][1], acc[mt][nt][3]);
            }
        }
    }
    // reduce across g (lane bits 2..4)
#pragma unroll
    for (int nt = 0; nt < 8; nt++)
#pragma unroll
        for (int j = 0; j < 2; j++) {
            float v = cmax[nt][j];
            v = fmaxf(v, __shfl_xor_sync(0xffffffffu, v, 4));
            v = fmaxf(v, __shfl_xor_sync(0xffffffffu, v, 8));
            v = fmaxf(v, __shfl_xor_sync(0xffffffffu, v, 16));
            cmax[nt][j] = v;
        }
    if (g == 0) {   // lanes 0..3 (lane == t)
#pragma unroll
        for (int nt = 0; nt < 8; nt++)
#pragma unroll
            for (int j = 0; j < 2; j++) {
                int col = n0 + wn * 64 + nt * 8 + 2 * t + j;
                atomicMaxFloat(&g_sentpre[(size_t)b * SDIM + col],
                               cmax[nt][j] + __ldg(&bc[col]));
            }
    }
}

// ---------------------------------------------------------------------------
// Kernel 4a: h[b][j] = dot(sigmoid(sentpre[b]), W1[j]) + b1[j]
// Grid (50, 64), 128 threads.
// ---------------------------------------------------------------------------
__global__ __launch_bounds__(128) void h_kernel(
    const float* __restrict__ W1, const float* __restrict__ b1)
{
    const int j = blockIdx.x;     // 0..49
    const int b = blockIdx.y;     // 0..63
    const float* pre = g_sentpre + (size_t)b * SDIM;
    const float* w   = W1 + (size_t)j * SDIM;

    float sum = 0.0f;
    for (int i = threadIdx.x; i < SDIM; i += 128) {
        float s = 1.0f / (1.0f + expf(-pre[i]));
        sum = fmaf(s, w[i], sum);
    }
    __shared__ float red[4];
#pragma unroll
    for (int o = 16; o > 0; o >>= 1) sum += __shfl_down_sync(0xffffffffu, sum, o);
    if ((threadIdx.x & 31) == 0) red[threadIdx.x >> 5] = sum;
    __syncthreads();
    if (threadIdx.x == 0)
        g_h[b * 64 + j] = red[0] + red[1] + red[2] + red[3] + b1[j];
}

// ---------------------------------------------------------------------------
// Kernel 4b: logits + log_softmax. One thread per batch.
// ---------------------------------------------------------------------------
__global__ void out_kernel(const float* __restrict__ W2, const float* __restrict__ b2,
                           float* __restrict__ out)
{
    int b = threadIdx.x;
    if (b >= BATCH) return;
    float l0 = b2[0], l1 = b2[1];
#pragma unroll
    for (int j = 0; j < 50; j++) {
        float h = g_h[b * 64 + j];
        l0 = fmaf(h, W2[j], l0);
        l1 = fmaf(h, W2[50 + j], l1);
    }
    float m   = fmaxf(l0, l1);
    float lse = m + logf(expf(l0 - m) + expf(l1 - m));
    out[b * NCLASS + 0] = l0 - lse;
    out[b * NCLASS + 1] = l1 - lse;
}

// ---------------------------------------------------------------------------
// kernel_launch
// inputs order: inputs(int32), emb_table, Wc, bc, W1, b1, W2, b2
// ---------------------------------------------------------------------------
extern "C" void kernel_launch(void* const* d_in, const int* in_sizes, int n_in,
                              void* d_out, int out_size) {
    const int*   inputs = (const int*)  d_in[0];
    const float* emb    = (const float*)d_in[1];
    const float* Wc     = (const float*)d_in[2];
    const float* bc     = (const float*)d_in[3];
    const float* W1     = (const float*)d_in[4];
    const float* b1     = (const float*)d_in[5];
    const float* W2     = (const float*)d_in[6];
    const float* b2     = (const float*)d_in[7];
    float* out = (float*)d_out;

    cudaFuncSetAttribute(conv_max_kernel,
                         cudaFuncAttributeMaxDynamicSharedMemorySize, SMEM_BYTES);

    gather_kernel<<<BATCH * SEQL, 128>>>(inputs, emb);
    init_kernel<<<(BATCH * SDIM + 255) / 256, 256>>>();

    dim3 grid(SDIM / BN, (SEQL + BM - 1) / BM, BATCH);   // (8, 2, 64)
    conv_max_kernel<<<grid, 128, SMEM_BYTES>>>(Wc, bc);

    h_kernel<<<dim3(50, BATCH), 128>>>(W1, b1);
    out_kernel<<<1, 64>>>(W2, b2, out);
}

// round 7
// speedup vs baseline: 7.1986x; 2.2001x over previous
#include <cuda_runtime.h>
#include <cuda_bf16.h>
#include <math_constants.h>
#include <cstdint>

// Problem constants
#define BATCH   64
#define SEQL    256
#define EDIM    512
#define SDIM    1024
#define KDIM    1024   // 2*E
#define NCLASS  2

// GEMM tile config (bf16 mma.sync m16n8k16)
#define BM 128
#define BN 128
#define BK 64                      // halves per k-tile (128 bytes of bf16)
#define LDT 72                     // padded smem row stride in halves (conflict-free)
#define TILE_HALVES (128 * LDT)    // one 128xBK tile
#define TILE_BYTES  (TILE_HALVES * 2)        // 18432
#define STAGE_HALVES (2 * TILE_HALVES)
#define SMEM_BYTES (2 * STAGE_HALVES * 2)    // 2 stages * (A+B) = 73728 B
#define NKT (KDIM / BK)            // 16

// Scratch (static device globals; no allocations allowed)
__device__ __nv_bfloat16 g_embs[BATCH * SEQL * EDIM];  // gathered embeddings (bf16)
__device__ __nv_bfloat16 g_wc[SDIM * KDIM];            // bf16 Wc
__device__ float g_sentpre[BATCH * SDIM];              // pre-sigmoid max accumulator
__device__ float g_h[BATCH * 64];                      // hidden (50 used)

__device__ __forceinline__ void atomicMaxFloat(float* addr, float val) {
    if (val >= 0.0f) atomicMax(reinterpret_cast<int*>(addr), __float_as_int(val));
    else             atomicMin(reinterpret_cast<unsigned int*>(addr), __float_as_uint(val));
}

__device__ __forceinline__ void mma_bf16(float c[4], const uint32_t a[4], const uint32_t b[2]) {
    asm volatile(
        "mma.sync.aligned.m16n8k16.row.col.f32.bf16.bf16.f32 "
        "{%0,%1,%2,%3}, {%4,%5,%6,%7}, {%8,%9}, {%0,%1,%2,%3};"
        : "+f"(c[0]), "+f"(c[1]), "+f"(c[2]), "+f"(c[3])
        : "r"(a[0]), "r"(a[1]), "r"(a[2]), "r"(a[3]), "r"(b[0]), "r"(b[1]));
}

__device__ __forceinline__ void cp_async16(uint32_t saddr, const void* gptr, bool pred) {
    int sz = pred ? 16 : 0;
    asm volatile("cp.async.cg.shared.global [%0], [%1], 16, %2;"
                 :: "r"(saddr), "l"(gptr), "r"(sz));
}

__device__ __forceinline__ uint32_t pack_bf16(float lo, float hi) {
    __nv_bfloat162 p = __floats2bfloat162_rn(lo, hi);
    return *reinterpret_cast<uint32_t*>(&p);
}

// ---------------------------------------------------------------------------
// Kernel 1a: embedding gather -> bf16
// ---------------------------------------------------------------------------
__global__ void gather_kernel(const int* __restrict__ inputs,
                              const float* __restrict__ emb_table) {
    int row = blockIdx.x;
    int tok = inputs[row];
    float4 v = reinterpret_cast<const float4*>(emb_table + (size_t)tok * EDIM)[threadIdx.x];
    uint2 o;
    o.x = pack_bf16(v.x, v.y);
    o.y = pack_bf16(v.z, v.w);
    reinterpret_cast<uint2*>(g_embs + (size_t)row * EDIM)[threadIdx.x] = o;
}

// ---------------------------------------------------------------------------
// Kernel 1b: Wc -> bf16
// ---------------------------------------------------------------------------
__global__ void wc_round_kernel(const float* __restrict__ Wc) {
    int i = blockIdx.x * blockDim.x + threadIdx.x;   // float4 index
    float4 v = reinterpret_cast<const float4*>(Wc)[i];
    uint2 o;
    o.x = pack_bf16(v.x, v.y);
    o.y = pack_bf16(v.z, v.w);
    reinterpret_cast<uint2*>(g_wc)[i] = o;
}

// ---------------------------------------------------------------------------
// Kernel 2: init max accumulator
// ---------------------------------------------------------------------------
__global__ void init_kernel() {
    int i = blockIdx.x * blockDim.x + threadIdx.x;
    if (i < BATCH * SDIM) g_sentpre[i] = -CUDART_INF_F;
}

// ---------------------------------------------------------------------------
// Kernel 3: BF16 tensor-core conv GEMM + fused max-pool.
//   A row l (1024 halves) = g_embs[b] + l*512 (overlapping rows, stride 512)
//   B = Wc bf16 [1024 x 1024] (n-major, k contiguous = col-major k x n)
// Block: 128 threads = 4 warps (2x2), warp tile 64x64, mma m16n8k16.
// Grid: (8 ntiles, 2 mtiles, 64 batches). 2-stage cp.async pipeline.
// ---------------------------------------------------------------------------
__global__ __launch_bounds__(128, 2) void conv_max_kernel(const float* __restrict__ bc)
{
    extern __shared__ __nv_bfloat16 sm[];

    const int b   = blockIdx.z;
    const int m0  = blockIdx.y * BM;
    const int n0  = blockIdx.x * BN;
    const int tid = threadIdx.x;
    const int lane = tid & 31;
    const int warp = tid >> 5;
    const int wm = warp >> 1;         // 0..1
    const int wn = warp & 1;          // 0..1
    const int g  = lane >> 2;         // 0..7
    const int t  = lane & 3;          // 0..3

    const __nv_bfloat16* Ag = g_embs + (size_t)b * SEQL * EDIM + (size_t)m0 * EDIM;
    const __nv_bfloat16* Bg = g_wc + (size_t)n0 * KDIM;

    const uint32_t smem_u32 = (uint32_t)__cvta_generic_to_shared(sm);

    // --- tile loader: stage st <- k-tile kt ---
    auto load_tile = [&](int kt, int st) {
        uint32_t base = smem_u32 + (uint32_t)st * (STAGE_HALVES * 2);
#pragma unroll
        for (int i = 0; i < 16; i++) {
            int c   = tid + 128 * i;            // 0..2047
            int row = (c & 1023) >> 3;          // 0..127
            int ch  = c & 7;                    // 16B chunk within 128B of k
            uint32_t daddr = base + (c < 1024 ? 0u : (uint32_t)TILE_BYTES)
                           + (uint32_t)(row * LDT * 2 + ch * 16);
            if (c < 1024) {
                bool av = (m0 + row) < (SEQL - 1);
                cp_async16(daddr, Ag + (size_t)row * EDIM + kt * BK + ch * 8, av);
            } else {
                cp_async16(daddr, Bg + (size_t)row * KDIM + kt * BK + ch * 8, true);
            }
        }
    };

    float acc[4][8][4];
#pragma unroll
    for (int mt = 0; mt < 4; mt++)
#pragma unroll
        for (int nt = 0; nt < 8; nt++)
#pragma unroll
            for (int q = 0; q < 4; q++) acc[mt][nt][q] = 0.0f;

    load_tile(0, 0);
    asm volatile("cp.async.commit_group;");

    for (int kt = 0; kt < NKT; ++kt) {
        if (kt + 1 < NKT) {
            load_tile(kt + 1, (kt + 1) & 1);
            asm volatile("cp.async.commit_group;");
            asm volatile("cp.async.wait_group 1;");
        } else {
            asm volatile("cp.async.wait_group 0;");
        }
        __syncthreads();

        // word-view of this stage's tiles
        const uint32_t* Aw = reinterpret_cast<const uint32_t*>(sm + (kt & 1) * STAGE_HALVES);
        const uint32_t* Bw = Aw + TILE_HALVES / 2;

#pragma unroll
        for (int ks = 0; ks < 4; ks++) {       // 4 ksteps of k16 per BK=64
            const int kw = ks * 8;             // word offset
            uint32_t af[4][4];
#pragma unroll
            for (int mt = 0; mt < 4; mt++) {
                const uint32_t* ap = Aw + (wm * 64 + mt * 16) * (LDT / 2) + kw;
                af[mt][0] = ap[(g    ) * (LDT / 2) + t    ];
                af[mt][1] = ap[(g + 8) * (LDT / 2) + t    ];
                af[mt][2] = ap[(g    ) * (LDT / 2) + t + 4];
                af[mt][3] = ap[(g + 8) * (LDT / 2) + t + 4];
            }
            uint32_t bf[8][2];
#pragma unroll
            for (int nt = 0; nt < 8; nt++) {
                const uint32_t* bp = Bw + (wn * 64 + nt * 8 + g) * (LDT / 2) + kw;
                bf[nt][0] = bp[t];
                bf[nt][1] = bp[t + 4];
            }
#pragma unroll
            for (int mt = 0; mt < 4; mt++)
#pragma unroll
                for (int nt = 0; nt < 8; nt++)
                    mma_bf16(acc[mt][nt], af[mt], bf[nt]);
        }
        __syncthreads();
    }

    // --- epilogue: per-thread column max over valid rows, shuffle-reduce over g ---
    float cmax[8][2];
#pragma unroll
    for (int nt = 0; nt < 8; nt++) { cmax[nt][0] = -CUDART_INF_F; cmax[nt][1] = -CUDART_INF_F; }

#pragma unroll
    for (int mt = 0; mt < 4; mt++) {
        int r0 = m0 + wm * 64 + mt * 16 + g;
        bool v0 = r0 < (SEQL - 1);
        bool v1 = (r0 + 8) < (SEQL - 1);
#pragma unroll
        for (int nt = 0; nt < 8; nt++) {
            if (v0) {
                cmax[nt][0] = fmaxf(cmax[nt][0], acc[mt][nt][0]);
                cmax[nt][1] = fmaxf(cmax[nt][1], acc[mt][nt][1]);
            }
            if (v1) {
                cmax[nt][0] = fmaxf(cmax[nt][0], acc[mt][nt][2]);
                cmax[nt][1] = fmaxf(cmax[nt][1], acc[mt][nt][3]);
            }
        }
    }
    // reduce across g (lane bits 2..4)
#pragma unroll
    for (int nt = 0; nt < 8; nt++)
#pragma unroll
        for (int j = 0; j < 2; j++) {
            float v = cmax[nt][j];
            v = fmaxf(v, __shfl_xor_sync(0xffffffffu, v, 4));
            v = fmaxf(v, __shfl_xor_sync(0xffffffffu, v, 8));
            v = fmaxf(v, __shfl_xor_sync(0xffffffffu, v, 16));
            cmax[nt][j] = v;
        }
    if (g == 0) {   // lanes 0..3 (lane == t)
#pragma unroll
        for (int nt = 0; nt < 8; nt++)
#pragma unroll
            for (int j = 0; j < 2; j++) {
                int col = n0 + wn * 64 + nt * 8 + 2 * t + j;
                atomicMaxFloat(&g_sentpre[(size_t)b * SDIM + col],
                               cmax[nt][j] + __ldg(&bc[col]));
            }
    }
}

// ---------------------------------------------------------------------------
// Kernel 4a: h[b][j] = dot(sigmoid(sentpre[b]), W1[j]) + b1[j]
// Grid (64), 256 threads (8 warps). sent cached in smem; float4 W1 loads.
// ---------------------------------------------------------------------------
__global__ __launch_bounds__(256) void h_kernel(
    const float* __restrict__ W1, const float* __restrict__ b1)
{
    const int b = blockIdx.x;
    __shared__ float sent[SDIM];
    for (int i = threadIdx.x; i < SDIM; i += 256) {
        float v = g_sentpre[(size_t)b * SDIM + i];
        sent[i] = 1.0f / (1.0f + expf(-v));
    }
    __syncthreads();

    const int w    = threadIdx.x >> 5;
    const int lane = threadIdx.x & 31;
    for (int j = w; j < 50; j += 8) {
        const float4* wrow = reinterpret_cast<const float4*>(W1 + (size_t)j * SDIM);
        float sum = 0.0f;
#pragma unroll
        for (int i = lane; i < SDIM / 4; i += 32) {
            float4 v = wrow[i];
            const float* s = &sent[i * 4];
            sum = fmaf(v.x, s[0], sum);
            sum = fmaf(v.y, s[1], sum);
            sum = fmaf(v.z, s[2], sum);
            sum = fmaf(v.w, s[3], sum);
        }
#pragma unroll
        for (int o = 16; o > 0; o >>= 1) sum += __shfl_down_sync(0xffffffffu, sum, o);
        if (lane == 0) g_h[b * 64 + j] = sum + b1[j];
    }
}

// ---------------------------------------------------------------------------
// Kernel 4b: logits + log_softmax. One thread per batch.
// ---------------------------------------------------------------------------
__global__ void out_kernel(const float* __restrict__ W2, const float* __restrict__ b2,
                           float* __restrict__ out)
{
    int b = threadIdx.x;
    if (b >= BATCH) return;
    float l0 = b2[0], l1 = b2[1];
#pragma unroll
    for (int j = 0; j < 50; j++) {
        float h = g_h[b * 64 + j];
        l0 = fmaf(h, W2[j], l0);
        l1 = fmaf(h, W2[50 + j], l1);
    }
    float m   = fmaxf(l0, l1);
    float lse = m + logf(expf(l0 - m) + expf(l1 - m));
    out[b * NCLASS + 0] = l0 - lse;
    out[b * NCLASS + 1] = l1 - lse;
}

// ---------------------------------------------------------------------------
// kernel_launch
// inputs order: inputs(int32), emb_table, Wc, bc, W1, b1, W2, b2
// ---------------------------------------------------------------------------
extern "C" void kernel_launch(void* const* d_in, const int* in_sizes, int n_in,
                              void* d_out, int out_size) {
    const int*   inputs = (const int*)  d_in[0];
    const float* emb    = (const float*)d_in[1];
    const float* Wc     = (const float*)d_in[2];
    const float* bc     = (const float*)d_in[3];
    const float* W1     = (const float*)d_in[4];
    const float* b1     = (const float*)d_in[5];
    const float* W2     = (const float*)d_in[6];
    const float* b2     = (const float*)d_in[7];
    float* out = (float*)d_out;

    cudaFuncSetAttribute(conv_max_kernel,
                         cudaFuncAttributeMaxDynamicSharedMemorySize, SMEM_BYTES);

    gather_kernel<<<BATCH * SEQL, 128>>>(inputs, emb);
    wc_round_kernel<<<(SDIM * KDIM / 4) / 256, 256>>>(Wc);
    init_kernel<<<(BATCH * SDIM + 255) / 256, 256>>>();

    dim3 grid(SDIM / BN, (SEQL + BM - 1) / BM, BATCH);   // (8, 2, 64)
    conv_max_kernel<<<grid, 128, SMEM_BYTES>>>(bc);

    h_kernel<<<BATCH, 256>>>(W1, b1);
    out_kernel<<<1, 64>>>(W2, b2, out);
}